// round 1
// baseline (speedup 1.0000x reference)
#include <cuda_runtime.h>

// ConsolidationDynamics: new_w = clamp(w + 0.001*tanh(MLP([w, cs, fs])), -10, 10)
// cs/fs are launch-constant scalars -> the update is a scalar function of w alone.
// Strategy: prep kernel tabulates delta(x) = 0.001*tanh(g(x)) on a 2048-segment
// grid over [-12, 12]; main kernel streams the 4096x4096 tensor with float4
// loads/stores and does a shared-memory LUT + linear interpolation.

#define TABLE_N 2048
#define RANGE_F 12.0f
#define SCALE_F (TABLE_N / (2.0f * RANGE_F))   // 85.33333

// (delta_i, delta_{i+1} - delta_i) per segment
__device__ float2 g_table[TABLE_N];

__device__ __forceinline__ float eval_delta(float x, float cs, float fs,
                                            const float* __restrict__ W1,
                                            const float* __restrict__ b1,
                                            const float* __restrict__ W2,
                                            float b2v) {
    float acc = b2v;
#pragma unroll
    for (int j = 0; j < 16; ++j) {
        float h = x * W1[j] + cs * W1[16 + j] + fs * W1[32 + j] + b1[j];
        h = fmaxf(h, 0.0f);
        acc += h * W2[j];
    }
    return 0.001f * tanhf(acc);
}

__global__ void prep_kernel(const float* __restrict__ cs_p,
                            const float* __restrict__ fs_p,
                            const float* __restrict__ W1,
                            const float* __restrict__ b1,
                            const float* __restrict__ W2,
                            const float* __restrict__ b2) {
    int i = blockIdx.x * blockDim.x + threadIdx.x;
    if (i >= TABLE_N) return;
    float cs = cs_p[0];
    float fs = fs_p[0];
    float b2v = b2[0];
    float x0 = -RANGE_F + (float)i / SCALE_F;
    float x1 = -RANGE_F + (float)(i + 1) / SCALE_F;
    float d0 = eval_delta(x0, cs, fs, W1, b1, W2, b2v);
    float d1 = eval_delta(x1, cs, fs, W1, b1, W2, b2v);
    g_table[i] = make_float2(d0, d1 - d0);
}

__global__ void __launch_bounds__(256)
main_kernel(const float4* __restrict__ in, float4* __restrict__ out, int n4) {
    __shared__ float2 tab[TABLE_N];

    // Copy 16 KB table into shared (1024 float4 moves, 4 per thread).
    {
        const float4* gt = reinterpret_cast<const float4*>(g_table);
        float4* st = reinterpret_cast<float4*>(tab);
#pragma unroll
        for (int i = threadIdx.x; i < TABLE_N / 2; i += 256) st[i] = gt[i];
    }
    __syncthreads();

    const int stride = gridDim.x * blockDim.x;
    for (int i = blockIdx.x * blockDim.x + threadIdx.x; i < n4; i += stride) {
        float4 v = in[i];
        float r[4] = {v.x, v.y, v.z, v.w};
#pragma unroll
        for (int e = 0; e < 4; ++e) {
            float x = r[e];
            float t = fmaf(x, SCALE_F, (float)(TABLE_N / 2));
            t = fminf(fmaxf(t, 0.0f), (float)TABLE_N - 1.0009765625f);
            int idx = (int)t;                 // t >= 0 -> trunc == floor
            float frac = t - (float)idx;
            float2 en = tab[idx];
            float y = x + fmaf(frac, en.y, en.x);
            r[e] = fminf(fmaxf(y, -10.0f), 10.0f);
        }
        out[i] = make_float4(r[0], r[1], r[2], r[3]);
    }
}

extern "C" void kernel_launch(void* const* d_in, const int* in_sizes, int n_in,
                              void* d_out, int out_size) {
    const float* w  = (const float*)d_in[0];
    const float* cs = (const float*)d_in[1];
    const float* fs = (const float*)d_in[2];
    const float* W1 = (const float*)d_in[3];
    const float* b1 = (const float*)d_in[4];
    const float* W2 = (const float*)d_in[5];
    const float* b2 = (const float*)d_in[6];
    (void)n_in;

    int n  = out_size;     // 4096*4096, divisible by 4
    int n4 = n / 4;

    prep_kernel<<<(TABLE_N + 255) / 256, 256>>>(cs, fs, W1, b1, W2, b2);
    // 148 SMs * 8 CTAs/SM; grid-stride covers n4 = 4,194,304 in ~14 iters/thread
    main_kernel<<<1184, 256>>>((const float4*)w, (float4*)d_out, n4);
}